// round 1
// baseline (speedup 1.0000x reference)
#include <cuda_runtime.h>
#include <math.h>

// Problem constants (fixed by the dataset)
#define B_  4096
#define IN_ 512
#define H_  1024
#define O_  256
#define L_  2
#define G_  3

// ---------------------------------------------------------------------------
// Scratch (device globals: allocation-guard safe)
// ---------------------------------------------------------------------------
static __device__ float g_h1  [(size_t)B_ * H_];        // relu(x @ i2d_w^T + b)      16 MB
static __device__ float g_gi  [(size_t)B_ * 3 * H_];    // input-side GRU gates       48 MB
static __device__ float g_gh  [(size_t)B_ * 3 * H_];    // hidden-side GRU gates      48 MB
static __device__ float g_hout[(size_t)B_ * H_];        // tanh(h_layer1)             16 MB

// ---------------------------------------------------------------------------
// SGEMM: C[M,N] = A[M,K] @ W[N,K]^T + bias[N], with optional activation.
// act: 0 = none, 1 = relu, 2 = softplus
// 128x128 block tile, BK=16, 256 threads, 8x8 per-thread microtile.
// All M,N,K here are multiples of the tiles, so no bounds checks.
// ---------------------------------------------------------------------------
__global__ __launch_bounds__(256, 2)
void sgemm_bias_act(const float* __restrict__ A,
                    const float* __restrict__ W,
                    const float* __restrict__ bias,
                    float* __restrict__ C,
                    int M, int N, int K, int act)
{
    __shared__ float As[16][132];   // [k][m], padded to dodge bank conflicts
    __shared__ float Bs[16][132];   // [k][n]

    const int tid = threadIdx.x;
    const int bm  = blockIdx.y * 128;
    const int bn  = blockIdx.x * 128;
    const int tx  = tid & 15;       // 16 thread cols
    const int ty  = tid >> 4;       // 16 thread rows

    float acc[8][8];
#pragma unroll
    for (int i = 0; i < 8; ++i)
#pragma unroll
        for (int j = 0; j < 8; ++j) acc[i][j] = 0.f;

    for (int kt = 0; kt < K; kt += 16) {
        // Load 128x16 A tile and 128x16 W tile (512 float4 each / 256 threads)
#pragma unroll
        for (int l = 0; l < 2; ++l) {
            int idx = tid + l * 256;
            int row = idx >> 2;              // 0..127
            int c4  = (idx & 3) << 2;        // 0,4,8,12
            float4 va = *reinterpret_cast<const float4*>(
                A + (size_t)(bm + row) * K + kt + c4);
            As[c4 + 0][row] = va.x; As[c4 + 1][row] = va.y;
            As[c4 + 2][row] = va.z; As[c4 + 3][row] = va.w;
            float4 vb = *reinterpret_cast<const float4*>(
                W + (size_t)(bn + row) * K + kt + c4);
            Bs[c4 + 0][row] = vb.x; Bs[c4 + 1][row] = vb.y;
            Bs[c4 + 2][row] = vb.z; Bs[c4 + 3][row] = vb.w;
        }
        __syncthreads();

#pragma unroll
        for (int k = 0; k < 16; ++k) {
            float ra[8], rb[8];
#pragma unroll
            for (int i = 0; i < 8; ++i) ra[i] = As[k][ty * 8 + i];
#pragma unroll
            for (int j = 0; j < 8; ++j) rb[j] = Bs[k][tx * 8 + j];
#pragma unroll
            for (int i = 0; i < 8; ++i)
#pragma unroll
                for (int j = 0; j < 8; ++j)
                    acc[i][j] = fmaf(ra[i], rb[j], acc[i][j]);
        }
        __syncthreads();
    }

    // Epilogue: bias + activation
#pragma unroll
    for (int i = 0; i < 8; ++i) {
        int m = bm + ty * 8 + i;
#pragma unroll
        for (int j = 0; j < 8; ++j) {
            int n = bn + tx * 8 + j;
            float v = acc[i][j] + bias[n];
            if (act == 1) {
                v = fmaxf(v, 0.f);
            } else if (act == 2) {
                v = (v > 20.f) ? v : log1pf(expf(v));  // softplus
            }
            C[(size_t)m * N + n] = v;
        }
    }
}

// ---------------------------------------------------------------------------
// GRU gate fusion (PyTorch gate order r,z,n; biases already inside gi/gh):
//   r = sigmoid(gi_r + gh_r); z = sigmoid(gi_z + gh_z)
//   n = tanh(gi_n + r * gh_n); h = (1-z)*n + z*h_prev
// Optionally also emits tanh(h) (final layer output feature).
// ---------------------------------------------------------------------------
__global__ void gru_gate_kernel(const float* __restrict__ gi,
                                const float* __restrict__ gh,
                                const float* __restrict__ h_prev,
                                float* __restrict__ h_new,
                                float* __restrict__ h_tanh)
{
    int idx = blockIdx.x * blockDim.x + threadIdx.x;
    if (idx >= B_ * H_) return;
    int b = idx >> 10;          // / H_
    int j = idx & (H_ - 1);     // % H_

    const float* gib = gi + (size_t)b * 3 * H_;
    const float* ghb = gh + (size_t)b * 3 * H_;

    float r = 1.f / (1.f + expf(-(gib[j]          + ghb[j])));
    float z = 1.f / (1.f + expf(-(gib[H_ + j]     + ghb[H_ + j])));
    float n = tanhf(gib[2 * H_ + j] + r * ghb[2 * H_ + j]);
    float hp = h_prev[idx];
    float h = (1.f - z) * n + z * hp;
    h_new[idx] = h;
    if (h_tanh) h_tanh[idx] = tanhf(h);
}

// ---------------------------------------------------------------------------
// In-place softmax over the G=3 mixture groups: pi[b, g*O + o], softmax over g.
// One thread per (b, o); disjoint triples so in-place is safe.
// ---------------------------------------------------------------------------
__global__ void pi_softmax_kernel(float* __restrict__ pi)
{
    int idx = blockIdx.x * blockDim.x + threadIdx.x;
    if (idx >= B_ * O_) return;
    int b = idx >> 8;           // / O_
    int o = idx & (O_ - 1);     // % O_
    float* p = pi + (size_t)b * G_ * O_ + o;
    float v0 = p[0], v1 = p[O_], v2 = p[2 * O_];
    float m = fmaxf(v0, fmaxf(v1, v2));
    float e0 = expf(v0 - m), e1 = expf(v1 - m), e2 = expf(v2 - m);
    float inv = 1.f / (e0 + e1 + e2);
    p[0] = e0 * inv; p[O_] = e1 * inv; p[2 * O_] = e2 * inv;
}

// ---------------------------------------------------------------------------
// Launch plumbing
// ---------------------------------------------------------------------------
static inline void launch_gemm(const float* A, const float* W, const float* bias,
                               float* C, int M, int N, int K, int act)
{
    dim3 grid(N / 128, M / 128);
    sgemm_bias_act<<<grid, 256>>>(A, W, bias, C, M, N, K, act);
}

extern "C" void kernel_launch(void* const* d_in, const int* in_sizes, int n_in,
                              void* d_out, int out_size)
{
    const float* x       = (const float*)d_in[0];   // [B, IN]
    const float* hidden  = (const float*)d_in[1];   // [L, B, H]
    const float* i2d_w   = (const float*)d_in[2];   // [H, IN]
    const float* i2d_b   = (const float*)d_in[3];   // [H]
    const float* w_ih    = (const float*)d_in[4];   // [L, 3H, H]
    const float* w_hh    = (const float*)d_in[5];   // [L, 3H, H]
    const float* b_ih    = (const float*)d_in[6];   // [L, 3H]
    const float* b_hh    = (const float*)d_in[7];   // [L, 3H]
    const float* mu_w    = (const float*)d_in[8];   // [G*O, H]
    const float* mu_b    = (const float*)d_in[9];   // [G*O]
    const float* sigma_w = (const float*)d_in[10];
    const float* sigma_b = (const float*)d_in[11];
    const float* pi_w    = (const float*)d_in[12];
    const float* pi_b    = (const float*)d_in[13];
    // d_in[14] = batch_size scalar (unused; shapes are fixed)

    float* out        = (float*)d_out;
    const size_t head_sz = (size_t)B_ * G_ * O_;    // 3,145,728
    float* out_mu     = out;
    float* out_sig    = out + head_sz;
    float* out_pi     = out + 2 * head_sz;
    float* out_hidden = out + 3 * head_sz;          // [L, B, H]

    float *h1, *gi, *gh, *hout;
    cudaGetSymbolAddress((void**)&h1,   g_h1);
    cudaGetSymbolAddress((void**)&gi,   g_gi);
    cudaGetSymbolAddress((void**)&gh,   g_gh);
    cudaGetSymbolAddress((void**)&hout, g_hout);

    const int eltB = (B_ * H_ + 255) / 256;
    const int smB  = (B_ * O_ + 255) / 256;

    // 1) h1 = relu(x @ i2d_w^T + i2d_b)
    launch_gemm(x, i2d_w, i2d_b, h1, B_, H_, IN_, /*relu*/1);

    // ---- GRU layer 0 ----
    launch_gemm(hidden,           w_hh,           b_hh,           gh, B_, 3 * H_, H_, 0);
    launch_gemm(h1,               w_ih,           b_ih,           gi, B_, 3 * H_, H_, 0);
    gru_gate_kernel<<<eltB, 256>>>(gi, gh, hidden, out_hidden, nullptr);

    // ---- GRU layer 1 ----
    const size_t l1w = (size_t)3 * H_ * H_;
    const size_t l1b = (size_t)3 * H_;
    const size_t lh  = (size_t)B_ * H_;
    launch_gemm(hidden + lh,      w_hh + l1w,     b_hh + l1b,     gh, B_, 3 * H_, H_, 0);
    launch_gemm(out_hidden,       w_ih + l1w,     b_ih + l1b,     gi, B_, 3 * H_, H_, 0);
    gru_gate_kernel<<<eltB, 256>>>(gi, gh, hidden + lh, out_hidden + lh, hout);

    // ---- MDN heads on hout = tanh(h_layer1) ----
    launch_gemm(hout, mu_w,    mu_b,    out_mu,  B_, G_ * O_, H_, 0);          // mu
    launch_gemm(hout, sigma_w, sigma_b, out_sig, B_, G_ * O_, H_, /*softplus*/2); // sigma
    launch_gemm(hout, pi_w,    pi_b,    out_pi,  B_, G_ * O_, H_, 0);          // pi logits
    pi_softmax_kernel<<<smB, 256>>>(out_pi);
}

// round 3
// speedup vs baseline: 1.6042x; 1.6042x over previous
#include <cuda_runtime.h>
#include <math.h>
#include <stdint.h>

// ============================================================================
// Problem constants
// ============================================================================
#define B_  4096
#define IN_ 512
#define H_  1024
#define O_  256
#define L_  2
#define G_  3

// ============================================================================
// GEMM tiling (mma.sync m16n8k8 tf32)
// ============================================================================
#define BM 128
#define BN 128
#define BK 32
#define PITCH 36                        // floats per smem row (conflict-free)
#define TILE_FLOATS (BM * PITCH)        // 4608 floats = 18432 B
#define SMEM_FLOATS (4 * TILE_FLOATS)   // A0,B0,A1,B1 = 73728 B
#define SMEM_BYTES  (SMEM_FLOATS * 4)

// ============================================================================
// Scratch (device globals)
// ============================================================================
static __device__ float g_xr   [(size_t)B_ * IN_];
static __device__ float g_hidr [(size_t)L_ * B_ * H_];
static __device__ float g_i2dwr[(size_t)H_ * IN_];
static __device__ float g_wihr [(size_t)L_ * 3 * H_ * H_];
static __device__ float g_whhr [(size_t)L_ * 3 * H_ * H_];
static __device__ float g_muwr [(size_t)G_ * O_ * H_];
static __device__ float g_sigwr[(size_t)G_ * O_ * H_];
static __device__ float g_piwr [(size_t)G_ * O_ * H_];
static __device__ float g_h1   [(size_t)B_ * H_];
static __device__ float g_gi   [(size_t)B_ * 3 * H_];
static __device__ float g_gh   [(size_t)B_ * 3 * H_];
static __device__ float g_h2r  [(size_t)B_ * H_];
static __device__ float g_houtr[(size_t)B_ * H_];

// ============================================================================
// Helpers
// ============================================================================
__device__ __forceinline__ float rtf32(float x) {   // round-to-nearest tf32
    uint32_t u;
    asm("cvt.rna.tf32.f32 %0, %1;" : "=r"(u) : "f"(x));
    return __uint_as_float(u);
}

__device__ __forceinline__ void cp_async16(uint32_t saddr, const void* gptr) {
    asm volatile("cp.async.cg.shared.global [%0], [%1], 16;"
                 :: "r"(saddr), "l"(gptr) : "memory");
}
__device__ __forceinline__ void cp_commit() {
    asm volatile("cp.async.commit_group;" ::: "memory");
}
__device__ __forceinline__ void cp_wait1() {
    asm volatile("cp.async.wait_group 1;" ::: "memory");
}
__device__ __forceinline__ void cp_wait0() {
    asm volatile("cp.async.wait_group 0;" ::: "memory");
}

__device__ __forceinline__ void mma_tf32(float c[4], const uint32_t a[4],
                                         const uint32_t b[2]) {
    asm volatile(
        "mma.sync.aligned.m16n8k8.row.col.f32.tf32.tf32.f32 "
        "{%0,%1,%2,%3}, {%4,%5,%6,%7}, {%8,%9}, {%0,%1,%2,%3};"
        : "+f"(c[0]), "+f"(c[1]), "+f"(c[2]), "+f"(c[3])
        : "r"(a[0]), "r"(a[1]), "r"(a[2]), "r"(a[3]), "r"(b[0]), "r"(b[1]));
}

// ============================================================================
// GEMM: C[M,N] = A[M,K] @ W[N,K]^T + bias[N], activation.
// act: 0 = none, 1 = relu + tf32-round, 2 = softplus
// A, W must contain tf32-rounded values. M,N,K multiples of 128/128/32.
// ============================================================================
__global__ __launch_bounds__(256)
void gemm_mma_tf32(const float* __restrict__ A, const float* __restrict__ W,
                   const float* __restrict__ bias, float* __restrict__ C,
                   int M, int N, int K, int act)
{
    extern __shared__ float smem[];
    float* sA[2] = { smem,                   smem + 2 * TILE_FLOATS };
    float* sB[2] = { smem + TILE_FLOATS,     smem + 3 * TILE_FLOATS };

    const int tid  = threadIdx.x;
    const int lane = tid & 31;
    const int wid  = tid >> 5;
    const int wm   = wid & 1;            // 2 warps along M
    const int wn   = wid >> 1;           // 4 warps along N
    const int bm   = blockIdx.y * BM;
    const int bn   = blockIdx.x * BN;

    // per-thread global-load assignment: 4 chunks of 16B for A and for B
    const int ldrow = tid >> 3;          // 0..31 (row block of 32 rows/iter? no:)
    // idx scheme: idx = tid + i*256, row = idx>>3 (0..127), kc = (idx&7)*4
    float acc[4][4][4];
#pragma unroll
    for (int i = 0; i < 4; ++i)
#pragma unroll
        for (int j = 0; j < 4; ++j)
#pragma unroll
            for (int q = 0; q < 4; ++q) acc[i][j][q] = 0.f;
    (void)ldrow;

    const int nTiles = K / BK;

    auto issue_loads = [&](int buf, int kt) {
        uint32_t baseA = (uint32_t)__cvta_generic_to_shared(sA[buf]);
        uint32_t baseB = (uint32_t)__cvta_generic_to_shared(sB[buf]);
#pragma unroll
        for (int i = 0; i < 4; ++i) {
            int idx = tid + i * 256;
            int row = idx >> 3;
            int kc  = (idx & 7) << 2;
            cp_async16(baseA + (row * PITCH + kc) * 4,
                       A + (size_t)(bm + row) * K + kt + kc);
            cp_async16(baseB + (row * PITCH + kc) * 4,
                       W + (size_t)(bn + row) * K + kt + kc);
        }
        cp_commit();
    };

    issue_loads(0, 0);

    const int lgrp = lane >> 2;          // 0..7
    const int lth  = lane & 3;           // 0..3

    for (int t = 0; t < nTiles; ++t) {
        if (t + 1 < nTiles) issue_loads((t + 1) & 1, (t + 1) * BK);
        if (t + 1 < nTiles) cp_wait1(); else cp_wait0();
        __syncthreads();

        const float* a_s = sA[t & 1];
        const float* b_s = sB[t & 1];

#pragma unroll
        for (int kk = 0; kk < BK; kk += 8) {
            uint32_t af[4][4];
            uint32_t bf[4][2];
#pragma unroll
            for (int mt = 0; mt < 4; ++mt) {
                int rm = wm * 64 + mt * 16 + lgrp;
                const float* p0 = a_s + rm * PITCH + kk + lth;
                const float* p1 = a_s + (rm + 8) * PITCH + kk + lth;
                af[mt][0] = __float_as_uint(p0[0]);
                af[mt][1] = __float_as_uint(p1[0]);
                af[mt][2] = __float_as_uint(p0[4]);
                af[mt][3] = __float_as_uint(p1[4]);
            }
#pragma unroll
            for (int nt = 0; nt < 4; ++nt) {
                int rn = wn * 32 + nt * 8 + lgrp;
                const float* p = b_s + rn * PITCH + kk + lth;
                bf[nt][0] = __float_as_uint(p[0]);
                bf[nt][1] = __float_as_uint(p[4]);
            }
#pragma unroll
            for (int mt = 0; mt < 4; ++mt)
#pragma unroll
                for (int nt = 0; nt < 4; ++nt)
                    mma_tf32(acc[mt][nt], af[mt], bf[nt]);
        }
        __syncthreads();
    }

    // Epilogue: bias + activation, float2 stores
#pragma unroll
    for (int nt = 0; nt < 4; ++nt) {
        int col = bn + wn * 32 + nt * 8 + 2 * lth;
        float bx = __ldg(bias + col);
        float by = __ldg(bias + col + 1);
#pragma unroll
        for (int mt = 0; mt < 4; ++mt) {
            int row = bm + wm * 64 + mt * 16 + lgrp;
            float2 v0, v1;
            v0.x = acc[mt][nt][0] + bx;  v0.y = acc[mt][nt][1] + by;
            v1.x = acc[mt][nt][2] + bx;  v1.y = acc[mt][nt][3] + by;
            if (act == 1) {
                v0.x = rtf32(fmaxf(v0.x, 0.f)); v0.y = rtf32(fmaxf(v0.y, 0.f));
                v1.x = rtf32(fmaxf(v1.x, 0.f)); v1.y = rtf32(fmaxf(v1.y, 0.f));
            } else if (act == 2) {
                v0.x = (v0.x > 20.f) ? v0.x : log1pf(expf(v0.x));
                v0.y = (v0.y > 20.f) ? v0.y : log1pf(expf(v0.y));
                v1.x = (v1.x > 20.f) ? v1.x : log1pf(expf(v1.x));
                v1.y = (v1.y > 20.f) ? v1.y : log1pf(expf(v1.y));
            }
            *reinterpret_cast<float2*>(C + (size_t)row * N + col)       = v0;
            *reinterpret_cast<float2*>(C + (size_t)(row + 8) * N + col) = v1;
        }
    }
}

// ============================================================================
// Elementwise kernels
// ============================================================================
__global__ void round_kernel(const float4* __restrict__ s, float4* __restrict__ d, int n4)
{
    int i = blockIdx.x * blockDim.x + threadIdx.x;
    if (i >= n4) return;
    float4 v = s[i];
    v.x = rtf32(v.x); v.y = rtf32(v.y); v.z = rtf32(v.z); v.w = rtf32(v.w);
    d[i] = v;
}

__device__ __forceinline__ float sigm(float x) { return 1.f / (1.f + expf(-x)); }

__global__ void gru_gate_kernel(const float4* __restrict__ gi,
                                const float4* __restrict__ gh,
                                const float4* __restrict__ hprev,
                                float4* __restrict__ hnew,
                                float4* __restrict__ hrnd,
                                float4* __restrict__ htanh)
{
    int idx = blockIdx.x * blockDim.x + threadIdx.x;   // [0, B*H/4)
    if (idx >= B_ * H_ / 4) return;
    int b  = idx >> 8;            // / (H_/4)
    int jj = idx & 255;
    const float4* gib = gi + (size_t)b * (3 * H_ / 4);
    const float4* ghb = gh + (size_t)b * (3 * H_ / 4);
    float4 ir = gib[jj], iz = gib[256 + jj], in_ = gib[512 + jj];
    float4 hr = ghb[jj], hz = ghb[256 + jj], hn  = ghb[512 + jj];
    float4 hp = hprev[idx];
    float4 h;
    {
        float r = sigm(ir.x + hr.x), z = sigm(iz.x + hz.x);
        float n = tanhf(in_.x + r * hn.x);
        h.x = (1.f - z) * n + z * hp.x;
    }
    {
        float r = sigm(ir.y + hr.y), z = sigm(iz.y + hz.y);
        float n = tanhf(in_.y + r * hn.y);
        h.y = (1.f - z) * n + z * hp.y;
    }
    {
        float r = sigm(ir.z + hr.z), z = sigm(iz.z + hz.z);
        float n = tanhf(in_.z + r * hn.z);
        h.z = (1.f - z) * n + z * hp.z;
    }
    {
        float r = sigm(ir.w + hr.w), z = sigm(iz.w + hz.w);
        float n = tanhf(in_.w + r * hn.w);
        h.w = (1.f - z) * n + z * hp.w;
    }
    hnew[idx] = h;
    if (hrnd) {
        float4 q; q.x = rtf32(h.x); q.y = rtf32(h.y); q.z = rtf32(h.z); q.w = rtf32(h.w);
        hrnd[idx] = q;
    }
    if (htanh) {
        float4 t;
        t.x = rtf32(tanhf(h.x)); t.y = rtf32(tanhf(h.y));
        t.z = rtf32(tanhf(h.z)); t.w = rtf32(tanhf(h.w));
        htanh[idx] = t;
    }
}

__global__ void pi_softmax_kernel(float* __restrict__ pi)
{
    int idx = blockIdx.x * blockDim.x + threadIdx.x;
    if (idx >= B_ * O_) return;
    int b = idx >> 8;
    int o = idx & (O_ - 1);
    float* p = pi + (size_t)b * G_ * O_ + o;
    float v0 = p[0], v1 = p[O_], v2 = p[2 * O_];
    float m = fmaxf(v0, fmaxf(v1, v2));
    float e0 = expf(v0 - m), e1 = expf(v1 - m), e2 = expf(v2 - m);
    float inv = 1.f / (e0 + e1 + e2);
    p[0] = e0 * inv; p[O_] = e1 * inv; p[2 * O_] = e2 * inv;
}

// ============================================================================
// Host
// ============================================================================
extern "C" void kernel_launch(void* const* d_in, const int* in_sizes, int n_in,
                              void* d_out, int out_size)
{
    const float* x       = (const float*)d_in[0];
    const float* hidden  = (const float*)d_in[1];
    const float* i2d_w   = (const float*)d_in[2];
    const float* i2d_b   = (const float*)d_in[3];
    const float* w_ih    = (const float*)d_in[4];
    const float* w_hh    = (const float*)d_in[5];
    const float* b_ih    = (const float*)d_in[6];
    const float* b_hh    = (const float*)d_in[7];
    const float* mu_w    = (const float*)d_in[8];
    const float* mu_b    = (const float*)d_in[9];
    const float* sigma_w = (const float*)d_in[10];
    const float* sigma_b = (const float*)d_in[11];
    const float* pi_w    = (const float*)d_in[12];
    const float* pi_b    = (const float*)d_in[13];

    float* out = (float*)d_out;
    const size_t head_sz = (size_t)B_ * G_ * O_;
    float* out_mu     = out;
    float* out_sig    = out + head_sz;
    float* out_pi     = out + 2 * head_sz;
    float* out_hidden = out + 3 * head_sz;

    float *xr, *hidr, *i2dwr, *wihr, *whhr, *muwr, *sigwr, *piwr;
    float *h1, *gi, *gh, *h2r, *houtr;
    cudaGetSymbolAddress((void**)&xr,    g_xr);
    cudaGetSymbolAddress((void**)&hidr,  g_hidr);
    cudaGetSymbolAddress((void**)&i2dwr, g_i2dwr);
    cudaGetSymbolAddress((void**)&wihr,  g_wihr);
    cudaGetSymbolAddress((void**)&whhr,  g_whhr);
    cudaGetSymbolAddress((void**)&muwr,  g_muwr);
    cudaGetSymbolAddress((void**)&sigwr, g_sigwr);
    cudaGetSymbolAddress((void**)&piwr,  g_piwr);
    cudaGetSymbolAddress((void**)&h1,    g_h1);
    cudaGetSymbolAddress((void**)&gi,    g_gi);
    cudaGetSymbolAddress((void**)&gh,    g_gh);
    cudaGetSymbolAddress((void**)&h2r,   g_h2r);
    cudaGetSymbolAddress((void**)&houtr, g_houtr);

    const size_t lw = (size_t)3 * H_ * H_;
    const size_t lb = (size_t)3 * H_;
    const size_t lh = (size_t)B_ * H_;

    static bool attr_set = false;
    if (!attr_set) {
        cudaFuncSetAttribute(gemm_mma_tf32,
                             cudaFuncAttributeMaxDynamicSharedMemorySize, SMEM_BYTES);
        attr_set = true;
    }

    auto gemm = [&](const float* A, const float* W, const float* bias,
                    float* C, int M, int N, int K, int act) {
        dim3 grid(N / BN, M / BM);
        gemm_mma_tf32<<<grid, 256, SMEM_BYTES>>>(A, W, bias, C, M, N, K, act);
    };
    auto rnd = [&](const float* s, float* d, size_t n) {
        int n4 = (int)(n / 4);
        round_kernel<<<(n4 + 255) / 256, 256>>>((const float4*)s, (float4*)d, n4);
    };

    const int gateGrid = (B_ * H_ / 4) / 256;   // 4096
    const int smGrid   = (B_ * O_) / 256;       // 4096

    // tf32 rounding prepass
    rnd(x,       xr,    (size_t)B_ * IN_);
    rnd(hidden,  hidr,  (size_t)L_ * B_ * H_);
    rnd(i2d_w,   i2dwr, (size_t)H_ * IN_);
    rnd(w_ih,    wihr,  (size_t)L_ * lw);
    rnd(w_hh,    whhr,  (size_t)L_ * lw);
    rnd(mu_w,    muwr,  (size_t)G_ * O_ * H_);
    rnd(sigma_w, sigwr, (size_t)G_ * O_ * H_);
    rnd(pi_w,    piwr,  (size_t)G_ * O_ * H_);

    // 1) h1 = round(relu(x @ i2d_w^T + b))
    gemm(xr, i2dwr, i2d_b, h1, B_, H_, IN_, 1);

    // ---- GRU layer 0 ----
    gemm(hidr,       whhr,      b_hh,      gh, B_, 3 * H_, H_, 0);
    gemm(h1,         wihr,      b_ih,      gi, B_, 3 * H_, H_, 0);
    gru_gate_kernel<<<gateGrid, 256>>>((const float4*)gi, (const float4*)gh,
                                       (const float4*)hidden,
                                       (float4*)out_hidden, (float4*)h2r, nullptr);

    // ---- GRU layer 1 ----
    gemm(hidr + lh,  whhr + lw, b_hh + lb, gh, B_, 3 * H_, H_, 0);
    gemm(h2r,        wihr + lw, b_ih + lb, gi, B_, 3 * H_, H_, 0);
    gru_gate_kernel<<<gateGrid, 256>>>((const float4*)gi, (const float4*)gh,
                                       (const float4*)(hidden + lh),
                                       (float4*)(out_hidden + lh), nullptr,
                                       (float4*)houtr);

    // ---- MDN heads ----
    gemm(houtr, muwr,  mu_b,    out_mu,  B_, G_ * O_, H_, 0);
    gemm(houtr, sigwr, sigma_b, out_sig, B_, G_ * O_, H_, 2);
    gemm(houtr, piwr,  pi_b,    out_pi,  B_, G_ * O_, H_, 0);
    pi_softmax_kernel<<<smGrid, 256>>>(out_pi);
}

// round 4
// speedup vs baseline: 6.2838x; 3.9170x over previous
#include <cuda_runtime.h>
#include <cuda_fp16.h>
#include <math.h>
#include <stdint.h>

// ============================================================================
// Problem constants
// ============================================================================
#define B_  4096
#define IN_ 512
#define H_  1024
#define O_  256
#define L_  2
#define G_  3
#define NH  (G_ * O_)        // 768 per head
#define NHEADS3 (3 * NH)     // 2304 fused head columns

// ============================================================================
// GEMM tiling (mma.sync m16n8k16 f16, ldmatrix feeds)
// ============================================================================
#define BM 128
#define BN 128
#define BK 32
#define PH 40                           // smem pitch in halves (80 B rows)
#define A_TILE_BYTES (BM * PH * 2)      // 10240
#define STG_BYTES    (2 * A_TILE_BYTES) // 20480 (A + B)
#define NSTG 3
#define SMEM_BYTES   (NSTG * STG_BYTES) // 61440

// ============================================================================
// Scratch (device globals; 16B-aligned for cp.async / vector access)
// ============================================================================
static __device__ __align__(256) __half g_xh    [(size_t)B_ * IN_];
static __device__ __align__(256) __half g_hidh  [(size_t)L_ * B_ * H_];
static __device__ __align__(256) __half g_i2dwh [(size_t)H_ * IN_];
static __device__ __align__(256) __half g_wihh  [(size_t)L_ * 3 * H_ * H_];
static __device__ __align__(256) __half g_whhh  [(size_t)L_ * 3 * H_ * H_];
static __device__ __align__(256) __half g_headwh[(size_t)NHEADS3 * H_];
static __device__ __align__(256) float  g_headb [NHEADS3];
static __device__ __align__(256) __half g_h1h   [(size_t)B_ * H_];
static __device__ __align__(256) float  g_gi    [(size_t)B_ * 3 * H_];
static __device__ __align__(256) float  g_gh    [(size_t)B_ * 3 * H_];
static __device__ __align__(256) __half g_h2h   [(size_t)B_ * H_];
static __device__ __align__(256) __half g_houth [(size_t)B_ * H_];

// ============================================================================
// PTX helpers
// ============================================================================
__device__ __forceinline__ void cp_async16(uint32_t saddr, const void* gptr) {
    asm volatile("cp.async.cg.shared.global [%0], [%1], 16;"
                 :: "r"(saddr), "l"(gptr) : "memory");
}
__device__ __forceinline__ void cp_commit() {
    asm volatile("cp.async.commit_group;" ::: "memory");
}
__device__ __forceinline__ void cp_wait1() {
    asm volatile("cp.async.wait_group 1;" ::: "memory");
}
__device__ __forceinline__ void cp_wait0() {
    asm volatile("cp.async.wait_group 0;" ::: "memory");
}

#define LDSM4(r, a) \
    asm volatile("ldmatrix.sync.aligned.m8n8.x4.shared.b16 {%0,%1,%2,%3}, [%4];" \
        : "=r"((r)[0]), "=r"((r)[1]), "=r"((r)[2]), "=r"((r)[3]) : "r"(a))

__device__ __forceinline__ void mma_f16(float c[4], const uint32_t a[4],
                                        uint32_t b0, uint32_t b1) {
    asm volatile(
        "mma.sync.aligned.m16n8k16.row.col.f32.f16.f16.f32 "
        "{%0,%1,%2,%3}, {%4,%5,%6,%7}, {%8,%9}, {%0,%1,%2,%3};"
        : "+f"(c[0]), "+f"(c[1]), "+f"(c[2]), "+f"(c[3])
        : "r"(a[0]), "r"(a[1]), "r"(a[2]), "r"(a[3]), "r"(b0), "r"(b1));
}

// ============================================================================
// GEMM: C[M,N] = A[M,K] @ W[N,K]^T + bias[N]
//   A, W are __half (row-major, K contiguous). Accumulate fp32.
//   act 0: fp32 out to Cf (stride N)
//   act 1: relu -> __half out to Ch (stride N)
//   act 2: fused-heads mode: N=2304, Cf = output base; segment s = col/768
//          writes Cf + s*B*768 + row*768 + (col - s*768); softplus on seg 1.
// M,N multiples of 128; K multiple of 32.
// ============================================================================
__global__ __launch_bounds__(256)
void gemm_f16(const __half* __restrict__ A, const __half* __restrict__ W,
              const float* __restrict__ bias, float* __restrict__ Cf,
              __half* __restrict__ Ch, int M, int N, int K, int act)
{
    extern __shared__ char smem_raw[];
    const uint32_t sbase = (uint32_t)__cvta_generic_to_shared(smem_raw);

    const int tid  = threadIdx.x;
    const int lane = tid & 31;
    const int wid  = tid >> 5;
    const int wm   = wid & 1;            // 2 warps along M (64 rows each)
    const int wn   = wid >> 1;           // 4 warps along N (32 cols each)
    const int bm   = blockIdx.y * BM;
    const int bn   = blockIdx.x * BN;

    float acc[4][4][4];
#pragma unroll
    for (int i = 0; i < 4; ++i)
#pragma unroll
        for (int j = 0; j < 4; ++j)
#pragma unroll
            for (int q = 0; q < 4; ++q) acc[i][j][q] = 0.f;

    // --- cp.async assignment: 2 x 16B chunks per thread for A and for B ---
    // idx = tid + i*256; row = idx>>2 (0..127); c8 = (idx&3)*8 halves
    auto issue = [&](int stg, int kt) {
        uint32_t sa = sbase + stg * STG_BYTES;
        uint32_t sb = sa + A_TILE_BYTES;
#pragma unroll
        for (int i = 0; i < 2; ++i) {
            int idx = tid + i * 256;
            int row = idx >> 2;
            int c8  = (idx & 3) << 3;
            uint32_t doff = (uint32_t)(row * PH + c8) * 2;
            cp_async16(sa + doff, A + (size_t)(bm + row) * K + kt + c8);
            cp_async16(sb + doff, W + (size_t)(bn + row) * K + kt + c8);
        }
        cp_commit();
    };

    const int nT = K / BK;
    issue(0, 0);
    if (nT > 1) issue(1, BK);
    else        cp_commit();             // keep group count consistent

    // --- ldmatrix lane addressing (pitch PH halves) ---
    // A x4: lane l -> row wm*64 + (l&15) (+ mt*16), col kk + ((l>>4)<<3)
    const uint32_t aOff = (uint32_t)(((wm * 64 + (lane & 15)) * PH +
                                      ((lane >> 4) << 3)) * 2);
    // B x4 (nt-pair p): lane l -> row wn*32 + ((l>>4)<<3) + (l&7) (+ p*16),
    //                   col kk + (((l>>3)&1)<<3)
    const uint32_t bOff = (uint32_t)(((wn * 32 + ((lane >> 4) << 3) + (lane & 7)) * PH +
                                      (((lane >> 3) & 1) << 3)) * 2);

    for (int t = 0; t < nT; ++t) {
        if (t + 1 < nT) cp_wait1(); else cp_wait0();
        __syncthreads();
        if (t + 2 < nT) issue((t + 2) % NSTG, (t + 2) * BK);

        uint32_t sa = sbase + (t % NSTG) * STG_BYTES;
        uint32_t sb = sa + A_TILE_BYTES;

#pragma unroll
        for (int kk = 0; kk < BK; kk += 16) {
            uint32_t af[4][4];
#pragma unroll
            for (int mt = 0; mt < 4; ++mt)
                LDSM4(af[mt], sa + aOff + (uint32_t)(mt * 16 * PH + kk) * 2);
            uint32_t bf[2][4];
#pragma unroll
            for (int p = 0; p < 2; ++p)
                LDSM4(bf[p], sb + bOff + (uint32_t)(p * 16 * PH + kk) * 2);
#pragma unroll
            for (int mt = 0; mt < 4; ++mt)
#pragma unroll
                for (int nt = 0; nt < 4; ++nt)
                    mma_f16(acc[mt][nt], af[mt],
                            bf[nt >> 1][(nt & 1) * 2],
                            bf[nt >> 1][(nt & 1) * 2 + 1]);
        }
        __syncthreads();
    }

    // --- Epilogue ---
    const int lgrp = lane >> 2;          // 0..7
    const int lth  = lane & 3;           // 0..3
#pragma unroll
    for (int nt = 0; nt < 4; ++nt) {
        int col = bn + wn * 32 + nt * 8 + 2 * lth;
        float bx = __ldg(bias + col);
        float by = __ldg(bias + col + 1);
#pragma unroll
        for (int mt = 0; mt < 4; ++mt) {
            int row = bm + wm * 64 + mt * 16 + lgrp;
            float v0x = acc[mt][nt][0] + bx, v0y = acc[mt][nt][1] + by;
            float v1x = acc[mt][nt][2] + bx, v1y = acc[mt][nt][3] + by;
            if (act == 1) {
                __half2 h0 = __floats2half2_rn(fmaxf(v0x, 0.f), fmaxf(v0y, 0.f));
                __half2 h1 = __floats2half2_rn(fmaxf(v1x, 0.f), fmaxf(v1y, 0.f));
                *reinterpret_cast<__half2*>(Ch + (size_t)row * N + col)       = h0;
                *reinterpret_cast<__half2*>(Ch + (size_t)(row + 8) * N + col) = h1;
            } else if (act == 0) {
                *reinterpret_cast<float2*>(Cf + (size_t)row * N + col)       = make_float2(v0x, v0y);
                *reinterpret_cast<float2*>(Cf + (size_t)(row + 8) * N + col) = make_float2(v1x, v1y);
            } else {
                int seg = col / NH;                   // tile never straddles segs
                if (seg == 1) {
                    v0x = (v0x > 20.f) ? v0x : log1pf(expf(v0x));
                    v0y = (v0y > 20.f) ? v0y : log1pf(expf(v0y));
                    v1x = (v1x > 20.f) ? v1x : log1pf(expf(v1x));
                    v1y = (v1y > 20.f) ? v1y : log1pf(expf(v1y));
                }
                float* dst = Cf + (size_t)seg * ((size_t)B_ * NH)
                                + (size_t)row * NH + (col - seg * NH);
                *reinterpret_cast<float2*>(dst)                = make_float2(v0x, v0y);
                *reinterpret_cast<float2*>(dst + (size_t)8 * NH) = make_float2(v1x, v1y);
            }
        }
    }
}

// ============================================================================
// Elementwise kernels
// ============================================================================
__global__ void f2h_kernel(const float4* __restrict__ s, __half2* __restrict__ d, int n4)
{
    int i = blockIdx.x * blockDim.x + threadIdx.x;
    if (i >= n4) return;
    float4 v = s[i];
    d[2 * i]     = __floats2half2_rn(v.x, v.y);
    d[2 * i + 1] = __floats2half2_rn(v.z, v.w);
}

__global__ void headb_copy(const float* __restrict__ mb, const float* __restrict__ sb,
                           const float* __restrict__ pb, float* __restrict__ dst)
{
    int i = blockIdx.x * blockDim.x + threadIdx.x;
    if (i >= NHEADS3) return;
    dst[i] = (i < NH) ? mb[i] : (i < 2 * NH) ? sb[i - NH] : pb[i - 2 * NH];
}

__device__ __forceinline__ float sigm(float x) { return 1.f / (1.f + expf(-x)); }

__global__ void gru_gate_kernel(const float4* __restrict__ gi,
                                const float4* __restrict__ gh,
                                const float4* __restrict__ hprev,
                                float4* __restrict__ hnew,
                                __half2* __restrict__ hh,      // optional: h as half
                                __half2* __restrict__ htanhh)  // optional: tanh(h) half
{
    int idx = blockIdx.x * blockDim.x + threadIdx.x;   // [0, B*H/4)
    if (idx >= B_ * H_ / 4) return;
    int b  = idx >> 8;
    int jj = idx & 255;
    const float4* gib = gi + (size_t)b * (3 * H_ / 4);
    const float4* ghb = gh + (size_t)b * (3 * H_ / 4);
    float4 ir = gib[jj], iz = gib[256 + jj], in_ = gib[512 + jj];
    float4 hr = ghb[jj], hz = ghb[256 + jj], hn  = ghb[512 + jj];
    float4 hp = hprev[idx];
    float4 h;
    {
        float r = sigm(ir.x + hr.x), z = sigm(iz.x + hz.x);
        float n = tanhf(in_.x + r * hn.x);
        h.x = (1.f - z) * n + z * hp.x;
    }
    {
        float r = sigm(ir.y + hr.y), z = sigm(iz.y + hz.y);
        float n = tanhf(in_.y + r * hn.y);
        h.y = (1.f - z) * n + z * hp.y;
    }
    {
        float r = sigm(ir.z + hr.z), z = sigm(iz.z + hz.z);
        float n = tanhf(in_.z + r * hn.z);
        h.z = (1.f - z) * n + z * hp.z;
    }
    {
        float r = sigm(ir.w + hr.w), z = sigm(iz.w + hz.w);
        float n = tanhf(in_.w + r * hn.w);
        h.w = (1.f - z) * n + z * hp.w;
    }
    hnew[idx] = h;
    if (hh) {
        hh[2 * idx]     = __floats2half2_rn(h.x, h.y);
        hh[2 * idx + 1] = __floats2half2_rn(h.z, h.w);
    }
    if (htanhh) {
        htanhh[2 * idx]     = __floats2half2_rn(tanhf(h.x), tanhf(h.y));
        htanhh[2 * idx + 1] = __floats2half2_rn(tanhf(h.z), tanhf(h.w));
    }
}

__global__ void pi_softmax_kernel(float* __restrict__ pi)
{
    int idx = blockIdx.x * blockDim.x + threadIdx.x;
    if (idx >= B_ * O_) return;
    int b = idx >> 8;
    int o = idx & (O_ - 1);
    float* p = pi + (size_t)b * NH + o;
    float v0 = p[0], v1 = p[O_], v2 = p[2 * O_];
    float m = fmaxf(v0, fmaxf(v1, v2));
    float e0 = expf(v0 - m), e1 = expf(v1 - m), e2 = expf(v2 - m);
    float inv = 1.f / (e0 + e1 + e2);
    p[0] = e0 * inv; p[O_] = e1 * inv; p[2 * O_] = e2 * inv;
}

// ============================================================================
// Host
// ============================================================================
extern "C" void kernel_launch(void* const* d_in, const int* in_sizes, int n_in,
                              void* d_out, int out_size)
{
    const float* x       = (const float*)d_in[0];
    const float* hidden  = (const float*)d_in[1];
    const float* i2d_w   = (const float*)d_in[2];
    const float* i2d_b   = (const float*)d_in[3];
    const float* w_ih    = (const float*)d_in[4];
    const float* w_hh    = (const float*)d_in[5];
    const float* b_ih    = (const float*)d_in[6];
    const float* b_hh    = (const float*)d_in[7];
    const float* mu_w    = (const float*)d_in[8];
    const float* mu_b    = (const float*)d_in[9];
    const float* sigma_w = (const float*)d_in[10];
    const float* sigma_b = (const float*)d_in[11];
    const float* pi_w    = (const float*)d_in[12];
    const float* pi_b    = (const float*)d_in[13];

    float* out = (float*)d_out;
    const size_t head_sz = (size_t)B_ * NH;
    float* out_pi     = out + 2 * head_sz;
    float* out_hidden = out + 3 * head_sz;

    __half *xh, *hidh, *i2dwh, *wihh, *whhh, *headwh, *h1h, *h2h, *houth;
    float  *headb, *gi, *gh;
    cudaGetSymbolAddress((void**)&xh,     g_xh);
    cudaGetSymbolAddress((void**)&hidh,   g_hidh);
    cudaGetSymbolAddress((void**)&i2dwh,  g_i2dwh);
    cudaGetSymbolAddress((void**)&wihh,   g_wihh);
    cudaGetSymbolAddress((void**)&whhh,   g_whhh);
    cudaGetSymbolAddress((void**)&headwh, g_headwh);
    cudaGetSymbolAddress((void**)&headb,  g_headb);
    cudaGetSymbolAddress((void**)&h1h,    g_h1h);
    cudaGetSymbolAddress((void**)&gi,     g_gi);
    cudaGetSymbolAddress((void**)&gh,     g_gh);
    cudaGetSymbolAddress((void**)&h2h,    g_h2h);
    cudaGetSymbolAddress((void**)&houth,  g_houth);

    const size_t lw = (size_t)3 * H_ * H_;
    const size_t lb = (size_t)3 * H_;
    const size_t lh = (size_t)B_ * H_;

    static bool attr_set = false;
    if (!attr_set) {
        cudaFuncSetAttribute(gemm_f16,
                             cudaFuncAttributeMaxDynamicSharedMemorySize, SMEM_BYTES);
        attr_set = true;
    }

    auto conv = [&](const float* s, __half* d, size_t n) {
        int n4 = (int)(n / 4);
        f2h_kernel<<<(n4 + 255) / 256, 256>>>((const float4*)s, (__half2*)d, n4);
    };
    auto gemm = [&](const __half* A, const __half* W, const float* bias,
                    float* Cf, __half* Ch, int M, int N, int K, int act) {
        dim3 grid(N / BN, M / BM);
        gemm_f16<<<grid, 256, SMEM_BYTES>>>(A, W, bias, Cf, Ch, M, N, K, act);
    };

    const int gateGrid = (B_ * H_ / 4) / 256;   // 4096
    const int smGrid   = (B_ * O_) / 256;       // 4096

    // ---- f32 -> f16 conversion prepass ----
    conv(x,       xh,     (size_t)B_ * IN_);
    conv(hidden,  hidh,   (size_t)L_ * B_ * H_);
    conv(i2d_w,   i2dwh,  (size_t)H_ * IN_);
    conv(w_ih,    wihh,   (size_t)L_ * lw);
    conv(w_hh,    whhh,   (size_t)L_ * lw);
    conv(mu_w,    headwh,                    (size_t)NH * H_);
    conv(sigma_w, headwh + (size_t)NH * H_,  (size_t)NH * H_);
    conv(pi_w,    headwh + (size_t)2 * NH * H_, (size_t)NH * H_);
    headb_copy<<<(NHEADS3 + 255) / 256, 256>>>(mu_b, sigma_b, pi_b, headb);

    // ---- 1) h1 = relu(x @ i2d_w^T + b) -> half ----
    gemm(xh, i2dwh, i2d_b, nullptr, h1h, B_, H_, IN_, 1);

    // ---- GRU layer 0 ----
    gemm(hidh,      whhh,      b_hh,      gh, nullptr, B_, 3 * H_, H_, 0);
    gemm(h1h,       wihh,      b_ih,      gi, nullptr, B_, 3 * H_, H_, 0);
    gru_gate_kernel<<<gateGrid, 256>>>((const float4*)gi, (const float4*)gh,
                                       (const float4*)hidden,
                                       (float4*)out_hidden, (__half2*)h2h, nullptr);

    // ---- GRU layer 1 ----
    gemm(hidh + lh, whhh + lw, b_hh + lb, gh, nullptr, B_, 3 * H_, H_, 0);
    gemm(h2h,       wihh + lw, b_ih + lb, gi, nullptr, B_, 3 * H_, H_, 0);
    gru_gate_kernel<<<gateGrid, 256>>>((const float4*)gi, (const float4*)gh,
                                       (const float4*)(hidden + lh),
                                       (float4*)(out_hidden + lh), nullptr,
                                       (__half2*)houth);

    // ---- MDN heads: one fused GEMM (mu | sigma | pi), N = 2304 ----
    gemm(houth, headwh, headb, out, nullptr, B_, NHEADS3, H_, 2);
    pi_softmax_kernel<<<smGrid, 256>>>(out_pi);
}